// round 11
// baseline (speedup 1.0000x reference)
#include <cuda_runtime.h>
#include <math.h>
#include <stdint.h>

// Problem constants
#define BN   32
#define CC   3072
#define KK   11
#define HW   784
#define NCLS 200
#define NCH  24           // c-chunks for k_ab
#define CCH  (CC / NCH)   // 128 channels per chunk (power of 2)

typedef unsigned long long ull;

// Scratch (device globals; no allocation allowed)
__device__ float g_ab_part[NCH * BN * KK * HW];   // 26.5 MB partial ab
__device__ float g_asq[KK];
__device__ float g_g[BN * CC];                    // sum_k feat_mod

// ---------------------------------------------------------------------------
// f32x2 + cp.async helpers
// ---------------------------------------------------------------------------
__device__ __forceinline__ void ffma2(ull& d, ull a, ull b) {
    asm("fma.rn.f32x2 %0, %1, %2, %0;" : "+l"(d) : "l"(a), "l"(b));
}
__device__ __forceinline__ ull pack2(float lo, float hi) {
    ull r; asm("mov.b64 %0, {%1, %2};" : "=l"(r) : "f"(lo), "f"(hi)); return r;
}
__device__ __forceinline__ float2 unpack2(ull v) {
    float2 r; asm("mov.b64 {%0, %1}, %2;" : "=f"(r.x), "=f"(r.y) : "l"(v)); return r;
}
__device__ __forceinline__ void cp16(uint32_t smem_dst, const void* gsrc) {
    asm volatile("cp.async.cg.shared.global [%0], [%1], 16;"
                 :: "r"(smem_dst), "l"(gsrc));
}
__device__ __forceinline__ void cp_commit() {
    asm volatile("cp.async.commit_group;");
}
template <int N>
__device__ __forceinline__ void cp_wait() {
    asm volatile("cp.async.wait_group %0;" :: "n"(N));
}
__device__ __forceinline__ uint32_t sptr(const void* p) {
    return (uint32_t)__cvta_generic_to_shared(p);
}

// ---------------------------------------------------------------------------
// Kernel 0: a_sq[k] = sum_c w_land[k,c]^2
// ---------------------------------------------------------------------------
__global__ void k_asq(const float* __restrict__ wl) {
    int k = blockIdx.x;
    int tid = threadIdx.x;
    float s = 0.f;
    for (int c = tid; c < CC; c += 128) {
        float w = wl[k * CC + c];
        s += w * w;
    }
    __shared__ float red[128];
    red[tid] = s;
    __syncthreads();
    for (int o = 64; o; o >>= 1) {
        if (tid < o) red[tid] += red[tid + o];
        __syncthreads();
    }
    if (tid == 0) g_asq[k] = red[0];
}

// ---------------------------------------------------------------------------
// Kernel 1: partial ab over a 128-channel chunk, ALL 784 pixels per block.
// grid (NCH=24, BN), block 196. Thread owns one ulonglong2 = 4 pixels.
// x staged via double-buffered cp.async: stage = 8 ch x 784 px = 25088 B.
// Smem: ws2 11264 + 2 x 25088 = 61440 B -> 3 blocks/SM.
// ---------------------------------------------------------------------------
#define AB_SCH    8
#define AB_STAGES (CCH / AB_SCH)   // 16
__global__ void __launch_bounds__(196, 3) k_ab(const float* __restrict__ x,
                                               const float* __restrict__ wl) {
    extern __shared__ char smem_ab[];
    ull* ws2 = (ull*)smem_ab;                       // [KK*CCH] {w,w} pairs
    char* xs[2] = { smem_ab + 11264, smem_ab + 11264 + 25088 };

    const int ch = blockIdx.x;
    const int b  = blockIdx.y;
    const int c0 = ch * CCH;
    const int tid = threadIdx.x;

    const float4* x4 = (const float4*)x;

    // stage s covers channels [s*8, s*8+8); each thread copies 8 float4
    // (one per channel), division-free mapping.
#define AB_KICK(s) {                                                          \
        uint32_t dbase_ = sptr(xs[(s) & 1]) + tid * 16;                       \
        const float4* src_ = x4 +                                             \
            ((size_t)(b * CC + c0 + (s) * AB_SCH) * 196 + tid);               \
        _Pragma("unroll")                                                     \
        for (int r = 0; r < AB_SCH; ++r)                                      \
            cp16(dbase_ + r * 3136, src_ + r * 196);                          \
        cp_commit();                                                          \
    }

    AB_KICK(0);

    // weights as duplicated pairs {w,w}: ws2[k*128 + c]
    for (int i = tid; i < KK * CCH; i += 196) {
        int k = i >> 7, c = i & 127;
        float w = wl[k * CC + c0 + c];
        ws2[i] = pack2(w, w);
    }

    AB_KICK(1);

    ull acc[KK][2];
#pragma unroll
    for (int k = 0; k < KK; ++k) { acc[k][0] = 0ull; acc[k][1] = 0ull; }

    __syncthreads();   // ws2 visible

    const ulonglong2* ws22 = (const ulonglong2*)ws2;   // [KK][CCH/2]

#pragma unroll 1
    for (int s = 0; s < AB_STAGES; ++s) {
        if (s < AB_STAGES - 1) cp_wait<1>(); else cp_wait<0>();
        __syncthreads();

        const ulonglong2* xsb2 = (const ulonglong2*)xs[s & 1]; // [8][196]
#pragma unroll
        for (int c4 = 0; c4 < AB_SCH; c4 += 4) {
            ulonglong2 xa = xsb2[(c4 + 0) * 196 + tid];
            ulonglong2 xb_ = xsb2[(c4 + 1) * 196 + tid];
            ulonglong2 xc = xsb2[(c4 + 2) * 196 + tid];
            ulonglong2 xd = xsb2[(c4 + 3) * 196 + tid];
            const int wq = (s * AB_SCH + c4) >> 1;
#pragma unroll
            for (int k = 0; k < KK; ++k) {
                ulonglong2 w01 = ws22[k * (CCH / 2) + wq];      // ch c4,c4+1
                ulonglong2 w23 = ws22[k * (CCH / 2) + wq + 1];  // ch c4+2,+3
                ffma2(acc[k][0], xa.x, w01.x); ffma2(acc[k][1], xa.y, w01.x);
                ffma2(acc[k][0], xb_.x, w01.y); ffma2(acc[k][1], xb_.y, w01.y);
                ffma2(acc[k][0], xc.x, w23.x); ffma2(acc[k][1], xc.y, w23.x);
                ffma2(acc[k][0], xd.x, w23.y); ffma2(acc[k][1], xd.y, w23.y);
            }
        }

        __syncthreads();
        if (s + 2 < AB_STAGES) AB_KICK(s + 2);
    }

    ulonglong2* gp2 = reinterpret_cast<ulonglong2*>(g_ab_part);
    size_t base2 = (size_t)(ch * BN + b) * KK * 196;
#pragma unroll
    for (int k = 0; k < KK; ++k) {
        ulonglong2 v; v.x = acc[k][0]; v.y = acc[k][1];
        gp2[base2 + (size_t)k * 196 + tid] = v;
    }
#undef AB_KICK
}

// ---------------------------------------------------------------------------
// Kernel 2: combine chunks, softmax over K (b_sq cancels), write maps.
// grid (BN, 4 pixel slices), block 196 (1 pixel per thread)
// ---------------------------------------------------------------------------
__global__ void k_softmax(float* __restrict__ maps) {
    const int b = blockIdx.x;
    const int p = blockIdx.y * 196 + threadIdx.x;

    __shared__ float asq[KK];
    if (threadIdx.x < KK) asq[threadIdx.x] = g_asq[threadIdx.x];
    __syncthreads();

    float s[KK];
#pragma unroll
    for (int k = 0; k < KK; ++k) s[k] = 0.f;

#pragma unroll 4
    for (int ch = 0; ch < NCH; ++ch) {
        size_t base = ((size_t)(ch * BN + b) * KK) * HW + p;
#pragma unroll
        for (int k = 0; k < KK; ++k)
            s[k] += g_ab_part[base + (size_t)k * HW];
    }
    float mx = -1e30f;
#pragma unroll
    for (int k = 0; k < KK; ++k) {
        s[k] = 2.f * s[k] - asq[k];
        mx = fmaxf(mx, s[k]);
    }
    float sum = 0.f;
#pragma unroll
    for (int k = 0; k < KK; ++k) {
        s[k] = __expf(s[k] - mx);
        sum += s[k];
    }
    float inv = 1.f / sum;
#pragma unroll
    for (int k = 0; k < KK; ++k)
        maps[((size_t)(b * KK + k)) * HW + p] = s[k] * inv;
}

// ---------------------------------------------------------------------------
// Kernel 3: feat[b,c,k] = (1/784) * sum_p maps[b,k,p] * x[b,c,p] * mod,
// plus g[b,c] = sum_k feat_mod.
// grid (96, 32), block 256 (8 warps x 4 channels). x via cp.async stages of
// 32 ch x 196 px; all smem reads are LDS.128 (ulonglong2 = 2 f32x2 pairs).
// Smem: maps 34496 + 2 x 25088 = 84672 B -> 2 blocks/SM.
// ---------------------------------------------------------------------------
#define FT_STAGES 4
__global__ void __launch_bounds__(256, 2) k_feat(const float* __restrict__ x,
                                                 const float* __restrict__ maps,
                                                 const float* __restrict__ mod,
                                                 float* __restrict__ feat) {
    extern __shared__ char smem_ft[];
    ull* maps_s = (ull*)smem_ft;                    // [KK*392] 34496 B
    char* xs[2] = { smem_ft + 34496, smem_ft + 34496 + 25088 };

    const int b   = (BN - 1) - blockIdx.y;
    const int tid = threadIdx.x;
    const int warp = tid >> 5, lane = tid & 31;
    const int c0 = blockIdx.x * 32;

    const float4* x4 = (const float4*)x;

    // stage s covers pixels [s*196, (s+1)*196) for 32 channels.
    // thread -> (sch = tid&31, q = (tid>>5) + 8r, q<49); division-free.
#define FT_KICK(s) {                                                          \
        const int sch_ = tid & 31;                                            \
        const int qh_  = tid >> 5;                                            \
        uint32_t dbase_ = sptr(xs[(s) & 1]) + sch_ * 784;                     \
        const float4* srow_ = x4 +                                            \
            ((size_t)(b * CC + c0 + sch_) * 196 + (s) * 49);                  \
        _Pragma("unroll")                                                     \
        for (int r = 0; r < 7; ++r) {                                         \
            int q = qh_ + 8 * r;                                              \
            if (q < 49) cp16(dbase_ + q * 16, srow_ + q);                     \
        }                                                                     \
        cp_commit();                                                          \
    }

    FT_KICK(0);

    // maps into smem while stage 0 flies
    const ull* mg = reinterpret_cast<const ull*>(maps + (size_t)b * KK * HW);
    for (int i = tid; i < KK * 392; i += 256) maps_s[i] = mg[i];

    FT_KICK(1);

    ull acc[4][KK];
#pragma unroll
    for (int j = 0; j < 4; ++j)
#pragma unroll
        for (int k = 0; k < KK; ++k) acc[j][k] = 0ull;

    __syncthreads();   // maps_s visible

    const ulonglong2* maps22 = (const ulonglong2*)maps_s;   // [KK][196]

#pragma unroll 1
    for (int s = 0; s < FT_STAGES; ++s) {
        if (s < FT_STAGES - 1) cp_wait<1>(); else cp_wait<0>();
        __syncthreads();

        const ulonglong2* xsb2 = (const ulonglong2*)xs[s & 1]; // [32][49]
        const int mq0 = s * 49;

        // q = lane (0..31)
        {
            const int q = lane;
            ulonglong2 x0 = xsb2[(4 * warp + 0) * 49 + q];
            ulonglong2 x1 = xsb2[(4 * warp + 1) * 49 + q];
            ulonglong2 x2 = xsb2[(4 * warp + 2) * 49 + q];
            ulonglong2 x3 = xsb2[(4 * warp + 3) * 49 + q];
#pragma unroll
            for (int k = 0; k < KK; ++k) {
                ulonglong2 m = maps22[k * 196 + mq0 + q];
                ffma2(acc[0][k], x0.x, m.x); ffma2(acc[0][k], x0.y, m.y);
                ffma2(acc[1][k], x1.x, m.x); ffma2(acc[1][k], x1.y, m.y);
                ffma2(acc[2][k], x2.x, m.x); ffma2(acc[2][k], x2.y, m.y);
                ffma2(acc[3][k], x3.x, m.x); ffma2(acc[3][k], x3.y, m.y);
            }
        }
        // q = 32 + lane (lane < 17)
        if (lane < 17) {
            const int q = 32 + lane;
            ulonglong2 x0 = xsb2[(4 * warp + 0) * 49 + q];
            ulonglong2 x1 = xsb2[(4 * warp + 1) * 49 + q];
            ulonglong2 x2 = xsb2[(4 * warp + 2) * 49 + q];
            ulonglong2 x3 = xsb2[(4 * warp + 3) * 49 + q];
#pragma unroll
            for (int k = 0; k < KK; ++k) {
                ulonglong2 m = maps22[k * 196 + mq0 + q];
                ffma2(acc[0][k], x0.x, m.x); ffma2(acc[0][k], x0.y, m.y);
                ffma2(acc[1][k], x1.x, m.x); ffma2(acc[1][k], x1.y, m.y);
                ffma2(acc[2][k], x2.x, m.x); ffma2(acc[2][k], x2.y, m.y);
                ffma2(acc[3][k], x3.x, m.x); ffma2(acc[3][k], x3.y, m.y);
            }
        }

        __syncthreads();
        if (s + 2 < FT_STAGES) FT_KICK(s + 2);
    }

    const float inv_hw = 1.f / (float)HW;
    const int cg = c0 + warp * 4;
#pragma unroll
    for (int j = 0; j < 4; ++j) {
        float gs = 0.f;
#pragma unroll
        for (int k = 0; k < KK; ++k) {
            float2 v = unpack2(acc[j][k]);
            float s = v.x + v.y;
#pragma unroll
            for (int o = 16; o; o >>= 1)
                s += __shfl_down_sync(0xffffffffu, s, o);
            if (lane == 0) {
                float r = s * inv_hw * mod[(cg + j) * KK + k];
                feat[((size_t)b * CC + cg + j) * KK + k] = r;
                gs += r;
            }
        }
        if (lane == 0) g_g[b * CC + cg + j] = gs;
    }
#undef FT_KICK
}

// ---------------------------------------------------------------------------
// Kernel 4: attn[b,k] = sum_p maps[b,k,p].  grid (BN, KK), block 256
// ---------------------------------------------------------------------------
__global__ void k_attn(const float* __restrict__ maps, float* __restrict__ attn) {
    const int b = blockIdx.x, k = blockIdx.y, tid = threadIdx.x;
    float s = 0.f;
    const float* mp = maps + ((size_t)b * KK + k) * HW;
    for (int i = tid; i < HW; i += 256) s += mp[i];
    __shared__ float red[256];
    red[tid] = s;
    __syncthreads();
    for (int o = 128; o; o >>= 1) {
        if (tid < o) red[tid] += red[tid + o];
        __syncthreads();
    }
    if (tid == 0) attn[b * KK + k] = red[0];
}

// ---------------------------------------------------------------------------
// Kernel 5: scores[b,n] = sum_c g[b,c] * w_cls[n,c]; 4 batches per block.
// grid (NCLS, BN/4), block 128
// ---------------------------------------------------------------------------
__global__ void k_scores(const float* __restrict__ wcls,
                         float* __restrict__ scores) {
    const int n = blockIdx.x;
    const int b0 = blockIdx.y * 4;
    const int tid = threadIdx.x;
    float s0 = 0.f, s1 = 0.f, s2 = 0.f, s3 = 0.f;
    const float* wn = wcls + (size_t)n * CC;
    for (int c = tid; c < CC; c += 128) {
        float w = wn[c];
        s0 = fmaf(w, g_g[(b0 + 0) * CC + c], s0);
        s1 = fmaf(w, g_g[(b0 + 1) * CC + c], s1);
        s2 = fmaf(w, g_g[(b0 + 2) * CC + c], s2);
        s3 = fmaf(w, g_g[(b0 + 3) * CC + c], s3);
    }
    __shared__ float red[4][128];
    red[0][tid] = s0; red[1][tid] = s1; red[2][tid] = s2; red[3][tid] = s3;
    __syncthreads();
    for (int o = 64; o; o >>= 1) {
        if (tid < o) {
            red[0][tid] += red[0][tid + o];
            red[1][tid] += red[1][tid + o];
            red[2][tid] += red[2][tid + o];
            red[3][tid] += red[3][tid + o];
        }
        __syncthreads();
    }
    if (tid == 0) {
#pragma unroll
        for (int j = 0; j < 4; ++j)
            scores[(b0 + j) * NCLS + n] = red[j][0];
    }
}

// ---------------------------------------------------------------------------
extern "C" void kernel_launch(void* const* d_in, const int* in_sizes, int n_in,
                              void* d_out, int out_size) {
    const float* x    = (const float*)d_in[0];
    const float* wl   = (const float*)d_in[1];
    const float* mod  = (const float*)d_in[2];
    const float* wcls = (const float*)d_in[3];

    float* out    = (float*)d_out;
    float* feat   = out;                                   // (B,C,K)
    float* scores = out + (size_t)BN * CC * KK;            // (B,NC)
    float* maps   = scores + (size_t)BN * NCLS;            // (B,K,HW)
    float* attn   = maps + (size_t)BN * KK * HW;           // (B,K)

    cudaFuncSetAttribute(k_ab,   cudaFuncAttributeMaxDynamicSharedMemorySize, 61440);
    cudaFuncSetAttribute(k_feat, cudaFuncAttributeMaxDynamicSharedMemorySize, 84672);

    k_asq<<<KK, 128>>>(wl);
    k_ab<<<dim3(NCH, BN), 196, 61440>>>(x, wl);
    k_softmax<<<dim3(BN, 4), 196>>>(maps);
    k_feat<<<dim3(CC / 32, BN), 256, 84672>>>(x, maps, mod, feat);
    k_attn<<<dim3(BN, KK), 256>>>(maps, attn);
    k_scores<<<dim3(NCLS, BN / 4), 128>>>(wcls, scores);
}

// round 12
// speedup vs baseline: 1.0756x; 1.0756x over previous
#include <cuda_runtime.h>
#include <math.h>
#include <stdint.h>

// Problem constants
#define BN   32
#define CC   3072
#define KK   11
#define HW   784
#define NCLS 200
#define NCH  12           // c-chunks for k_ab
#define CCH  (CC / NCH)   // 256 channels per chunk

typedef unsigned long long ull;

// Scratch (device globals; no allocation allowed)
__device__ float g_ab_part[NCH * BN * KK * HW];   // 13.2 MB partial ab
__device__ float g_asq[KK];
__device__ float g_g[BN * CC];                    // sum_k feat_mod

// ---------------------------------------------------------------------------
// f32x2 + cp.async helpers
// ---------------------------------------------------------------------------
__device__ __forceinline__ void ffma2(ull& d, ull a, ull b) {
    asm("fma.rn.f32x2 %0, %1, %2, %0;" : "+l"(d) : "l"(a), "l"(b));
}
__device__ __forceinline__ ull pack2(float lo, float hi) {
    ull r; asm("mov.b64 %0, {%1, %2};" : "=l"(r) : "f"(lo), "f"(hi)); return r;
}
__device__ __forceinline__ float2 unpack2(ull v) {
    float2 r; asm("mov.b64 {%0, %1}, %2;" : "=f"(r.x), "=f"(r.y) : "l"(v)); return r;
}
__device__ __forceinline__ void cp16(uint32_t smem_dst, const void* gsrc) {
    asm volatile("cp.async.cg.shared.global [%0], [%1], 16;"
                 :: "r"(smem_dst), "l"(gsrc));
}
__device__ __forceinline__ void cp_commit() {
    asm volatile("cp.async.commit_group;");
}
template <int N>
__device__ __forceinline__ void cp_wait() {
    asm volatile("cp.async.wait_group %0;" :: "n"(N));
}
__device__ __forceinline__ uint32_t sptr(const void* p) {
    return (uint32_t)__cvta_generic_to_shared(p);
}

// ---------------------------------------------------------------------------
// Kernel 0: a_sq[k] = sum_c w_land[k,c]^2
// ---------------------------------------------------------------------------
__global__ void k_asq(const float* __restrict__ wl) {
    int k = blockIdx.x;
    int tid = threadIdx.x;
    float s = 0.f;
    for (int c = tid; c < CC; c += 128) {
        float w = wl[k * CC + c];
        s += w * w;
    }
    __shared__ float red[128];
    red[tid] = s;
    __syncthreads();
    for (int o = 64; o; o >>= 1) {
        if (tid < o) red[tid] += red[tid + o];
        __syncthreads();
    }
    if (tid == 0) g_asq[k] = red[0];
}

// ---------------------------------------------------------------------------
// Kernel 1 (R7 version — measured ~3.3 TB/s): partial ab over a 256-channel
// chunk, half the pixels per block. grid (NCH, BN, 2), block 196.
// x staged via double-buffered cp.async (16 ch x 392 px = 25 KB per stage,
// 16 stages). Smem: ws2 22528 + 2 x 25088 = 72704 B -> 3 blocks/SM.
// ---------------------------------------------------------------------------
#define AB_STAGES 16
#define AB_SCH    16              // channels per stage
__global__ void __launch_bounds__(196, 3) k_ab(const float* __restrict__ x,
                                               const float* __restrict__ wl) {
    extern __shared__ char smem_ab[];
    ull* ws2 = (ull*)smem_ab;                       // [KK*CCH] 22528 B
    ull* xs[2] = { (ull*)(smem_ab + 22528),
                   (ull*)(smem_ab + 22528 + 25088) };

    const int ch = blockIdx.x;
    const int b  = blockIdx.y;
    const int ph = blockIdx.z;             // pixel half 0/1
    const int c0 = ch * CCH;
    const int tid = threadIdx.x;

    const float4* x4 = (const float4*)x;

#define AB_KICK(s) {                                                          \
        const int buf_ = (s) & 1;                                             \
        uint32_t dbase_ = sptr(xs[buf_]);                                     \
        _Pragma("unroll")                                                     \
        for (int r = 0; r < 8; ++r) {                                         \
            int ci = r * 196 + tid;                                           \
            int sch = ci / 98, p4 = ci - sch * 98;                            \
            const float4* src = x4 +                                          \
                ((size_t)(b * CC + c0 + (s) * AB_SCH + sch) * 196             \
                 + ph * 98 + p4);                                             \
            cp16(dbase_ + sch * 1568 + p4 * 16, src);                         \
        }                                                                     \
        cp_commit();                                                          \
    }

    AB_KICK(0);

    for (int i = tid; i < KK * CCH; i += 196) {
        int k = i >> 8, c = i & (CCH - 1);
        float w = wl[k * CC + c0 + c];
        ws2[i] = pack2(w, w);
    }

    AB_KICK(1);

    ull acc[KK];
#pragma unroll
    for (int k = 0; k < KK; ++k) acc[k] = 0ull;

    __syncthreads();   // ws2 visible

#pragma unroll 1
    for (int s = 0; s < AB_STAGES; ++s) {
        if (s < AB_STAGES - 1) cp_wait<1>(); else cp_wait<0>();
        __syncthreads();

        const ull* xsb = xs[s & 1];
        const int wbase = s * AB_SCH;
#pragma unroll
        for (int c4 = 0; c4 < AB_SCH; c4 += 4) {
            ull xa = xsb[(c4 + 0) * 196 + tid];
            ull xb_ = xsb[(c4 + 1) * 196 + tid];
            ull xc = xsb[(c4 + 2) * 196 + tid];
            ull xd = xsb[(c4 + 3) * 196 + tid];
#pragma unroll
            for (int k = 0; k < KK; ++k) {
                const ulonglong2* wp =
                    (const ulonglong2*)&ws2[k * CCH + wbase + c4];
                ulonglong2 w01 = wp[0];
                ulonglong2 w23 = wp[1];
                ffma2(acc[k], xa, w01.x); ffma2(acc[k], xb_, w01.y);
                ffma2(acc[k], xc, w23.x); ffma2(acc[k], xd, w23.y);
            }
        }

        __syncthreads();
        if (s + 2 < AB_STAGES) AB_KICK(s + 2);
    }

    ull* gp = reinterpret_cast<ull*>(g_ab_part);
    size_t base = ((size_t)(ch * BN + b) * KK) * HW;
    int po = ph * 196 + tid;
#pragma unroll
    for (int k = 0; k < KK; ++k)
        gp[(base + (size_t)k * HW) / 2 + po] = acc[k];
#undef AB_KICK
}

// ---------------------------------------------------------------------------
// Kernel 2: combine chunks, softmax over K (b_sq cancels), write maps.
// grid (BN, 4 pixel slices), block 196 (1 pixel per thread)
// ---------------------------------------------------------------------------
__global__ void k_softmax(float* __restrict__ maps) {
    const int b = blockIdx.x;
    const int p = blockIdx.y * 196 + threadIdx.x;

    __shared__ float asq[KK];
    if (threadIdx.x < KK) asq[threadIdx.x] = g_asq[threadIdx.x];
    __syncthreads();

    float s[KK];
#pragma unroll
    for (int k = 0; k < KK; ++k) s[k] = 0.f;

#pragma unroll
    for (int ch = 0; ch < NCH; ++ch) {
        size_t base = ((size_t)(ch * BN + b) * KK) * HW + p;
#pragma unroll
        for (int k = 0; k < KK; ++k)
            s[k] += g_ab_part[base + (size_t)k * HW];
    }
    float mx = -1e30f;
#pragma unroll
    for (int k = 0; k < KK; ++k) {
        s[k] = 2.f * s[k] - asq[k];
        mx = fmaxf(mx, s[k]);
    }
    float sum = 0.f;
#pragma unroll
    for (int k = 0; k < KK; ++k) {
        s[k] = __expf(s[k] - mx);
        sum += s[k];
    }
    float inv = 1.f / sum;
#pragma unroll
    for (int k = 0; k < KK; ++k)
        maps[((size_t)(b * KK + k)) * HW + p] = s[k] * inv;
}

// ---------------------------------------------------------------------------
// Kernel 3: feat[b,c,k] = (1/784) * sum_p maps[b,k,p] * x[b,c,p] * mod,
// plus g[b,c] = sum_k feat_mod.
// NEW SHAPE: 16 channels per block, 8 warps (2 ch/warp), triple-buffered
// cp.async stages of 16 ch x 196 px = 12.25 KB. Smem total
// 34496 + 3*12544 = 72128 B -> 3 blocks/SM (24 warps). All LDS.128.
// grid (CC/16 = 192, BN).
// ---------------------------------------------------------------------------
#define FT_STAGES 4
__global__ void __launch_bounds__(256, 3) k_feat(const float* __restrict__ x,
                                                 const float* __restrict__ maps,
                                                 const float* __restrict__ mod,
                                                 float* __restrict__ feat) {
    extern __shared__ char smem_ft[];
    ull* maps_s = (ull*)smem_ft;                    // [KK*392] 34496 B
    char* xsb[3] = { smem_ft + 34496,
                     smem_ft + 34496 + 12544,
                     smem_ft + 34496 + 25088 };

    const int b   = (BN - 1) - blockIdx.y;
    const int tid = threadIdx.x;
    const int warp = tid >> 5, lane = tid & 31;
    const int c0 = blockIdx.x * 16;

    const float4* x4 = (const float4*)x;

    // stage s covers pixels [s*196, (s+1)*196) for the block's 16 channels.
    // thread -> channel tid>>4, quad (tid&15)+16r (q<49). Division-free.
#define FT_KICK(s) {                                                          \
        const int sch_ = tid >> 4;                                            \
        const int qh_  = tid & 15;                                            \
        uint32_t dbase_ = sptr(xsb[(s) % 3]) + sch_ * 784;                    \
        const float4* srow_ = x4 +                                            \
            ((size_t)(b * CC + c0 + sch_) * 196 + (s) * 49);                  \
        _Pragma("unroll")                                                     \
        for (int r = 0; r < 4; ++r) {                                         \
            int q = qh_ + 16 * r;                                             \
            if (q < 49) cp16(dbase_ + q * 16, srow_ + q);                     \
        }                                                                     \
        cp_commit();                                                          \
    }

    FT_KICK(0);
    FT_KICK(1);

    // maps into smem while stages fly
    const ull* mg = reinterpret_cast<const ull*>(maps + (size_t)b * KK * HW);
    for (int i = tid; i < KK * 392; i += 256) maps_s[i] = mg[i];

    FT_KICK(2);

    ull acc[2][KK];
#pragma unroll
    for (int j = 0; j < 2; ++j)
#pragma unroll
        for (int k = 0; k < KK; ++k) acc[j][k] = 0ull;

    __syncthreads();   // maps_s visible

    const ulonglong2* maps22 = (const ulonglong2*)maps_s;   // [KK][196]
    const int ch0 = 2 * warp;

#pragma unroll 1
    for (int s = 0; s < FT_STAGES; ++s) {
        // groups issued so far: min(4, s+3); need group s complete
        if (s <= FT_STAGES - 3)      cp_wait<2>();
        else if (s == FT_STAGES - 2) cp_wait<1>();
        else                         cp_wait<0>();
        __syncthreads();

        const ulonglong2* xq = (const ulonglong2*)xsb[s % 3]; // [16][49]
        const int mq0 = s * 49;

        {   // q = lane (0..31, all < 49)
            const int q = lane;
            ulonglong2 xa = xq[ch0 * 49 + q];
            ulonglong2 xbv = xq[(ch0 + 1) * 49 + q];
#pragma unroll
            for (int k = 0; k < KK; ++k) {
                ulonglong2 m = maps22[k * 196 + mq0 + q];
                ffma2(acc[0][k], xa.x, m.x); ffma2(acc[0][k], xa.y, m.y);
                ffma2(acc[1][k], xbv.x, m.x); ffma2(acc[1][k], xbv.y, m.y);
            }
        }
        if (lane < 17) {   // q = 32..48
            const int q = 32 + lane;
            ulonglong2 xa = xq[ch0 * 49 + q];
            ulonglong2 xbv = xq[(ch0 + 1) * 49 + q];
#pragma unroll
            for (int k = 0; k < KK; ++k) {
                ulonglong2 m = maps22[k * 196 + mq0 + q];
                ffma2(acc[0][k], xa.x, m.x); ffma2(acc[0][k], xa.y, m.y);
                ffma2(acc[1][k], xbv.x, m.x); ffma2(acc[1][k], xbv.y, m.y);
            }
        }

        __syncthreads();
        if (s + 3 < FT_STAGES) FT_KICK(s + 3);
    }

    const float inv_hw = 1.f / (float)HW;
#pragma unroll
    for (int j = 0; j < 2; ++j) {
        const int c = c0 + ch0 + j;
        float gs = 0.f;
#pragma unroll
        for (int k = 0; k < KK; ++k) {
            float2 v = unpack2(acc[j][k]);
            float s = v.x + v.y;
#pragma unroll
            for (int o = 16; o; o >>= 1)
                s += __shfl_down_sync(0xffffffffu, s, o);
            if (lane == 0) {
                float r = s * inv_hw * mod[c * KK + k];
                feat[((size_t)b * CC + c) * KK + k] = r;
                gs += r;
            }
        }
        if (lane == 0) g_g[b * CC + c] = gs;
    }
#undef FT_KICK
}

// ---------------------------------------------------------------------------
// Kernel 4: attn[b,k] = sum_p maps[b,k,p].  grid (BN, KK), block 256
// ---------------------------------------------------------------------------
__global__ void k_attn(const float* __restrict__ maps, float* __restrict__ attn) {
    const int b = blockIdx.x, k = blockIdx.y, tid = threadIdx.x;
    float s = 0.f;
    const float* mp = maps + ((size_t)b * KK + k) * HW;
    for (int i = tid; i < HW; i += 256) s += mp[i];
    __shared__ float red[256];
    red[tid] = s;
    __syncthreads();
    for (int o = 128; o; o >>= 1) {
        if (tid < o) red[tid] += red[tid + o];
        __syncthreads();
    }
    if (tid == 0) attn[b * KK + k] = red[0];
}

// ---------------------------------------------------------------------------
// Kernel 5: scores[b,n] = sum_c g[b,c] * w_cls[n,c]; 4 batches per block.
// grid (NCLS, BN/4), block 128
// ---------------------------------------------------------------------------
__global__ void k_scores(const float* __restrict__ wcls,
                         float* __restrict__ scores) {
    const int n = blockIdx.x;
    const int b0 = blockIdx.y * 4;
    const int tid = threadIdx.x;
    float s0 = 0.f, s1 = 0.f, s2 = 0.f, s3 = 0.f;
    const float* wn = wcls + (size_t)n * CC;
    for (int c = tid; c < CC; c += 128) {
        float w = wn[c];
        s0 = fmaf(w, g_g[(b0 + 0) * CC + c], s0);
        s1 = fmaf(w, g_g[(b0 + 1) * CC + c], s1);
        s2 = fmaf(w, g_g[(b0 + 2) * CC + c], s2);
        s3 = fmaf(w, g_g[(b0 + 3) * CC + c], s3);
    }
    __shared__ float red[4][128];
    red[0][tid] = s0; red[1][tid] = s1; red[2][tid] = s2; red[3][tid] = s3;
    __syncthreads();
    for (int o = 64; o; o >>= 1) {
        if (tid < o) {
            red[0][tid] += red[0][tid + o];
            red[1][tid] += red[1][tid + o];
            red[2][tid] += red[2][tid + o];
            red[3][tid] += red[3][tid + o];
        }
        __syncthreads();
    }
    if (tid == 0) {
#pragma unroll
        for (int j = 0; j < 4; ++j)
            scores[(b0 + j) * NCLS + n] = red[j][0];
    }
}

// ---------------------------------------------------------------------------
extern "C" void kernel_launch(void* const* d_in, const int* in_sizes, int n_in,
                              void* d_out, int out_size) {
    const float* x    = (const float*)d_in[0];
    const float* wl   = (const float*)d_in[1];
    const float* mod  = (const float*)d_in[2];
    const float* wcls = (const float*)d_in[3];

    float* out    = (float*)d_out;
    float* feat   = out;                                   // (B,C,K)
    float* scores = out + (size_t)BN * CC * KK;            // (B,NC)
    float* maps   = scores + (size_t)BN * NCLS;            // (B,K,HW)
    float* attn   = maps + (size_t)BN * KK * HW;           // (B,K)

    cudaFuncSetAttribute(k_ab,   cudaFuncAttributeMaxDynamicSharedMemorySize, 72704);
    cudaFuncSetAttribute(k_feat, cudaFuncAttributeMaxDynamicSharedMemorySize, 72128);

    k_asq<<<KK, 128>>>(wl);
    k_ab<<<dim3(NCH, BN, 2), 196, 72704>>>(x, wl);
    k_softmax<<<dim3(BN, 4), 196>>>(maps);
    k_feat<<<dim3(CC / 16, BN), 256, 72128>>>(x, maps, mod, feat);
    k_attn<<<dim3(BN, KK), 256>>>(maps, attn);
    k_scores<<<dim3(NCLS, BN / 4), 128>>>(wcls, scores);
}

// round 15
// speedup vs baseline: 1.5574x; 1.4479x over previous
#include <cuda_runtime.h>
#include <math.h>
#include <stdint.h>

// Problem constants
#define BN   32
#define CC   3072
#define KK   11
#define HW   784
#define NCLS 200
#define NCH  12           // c-chunks for k_ab
#define CCH  (CC / NCH)   // 256 channels per chunk

typedef unsigned long long ull;

// Scratch (device globals; no allocation allowed)
__device__ float g_ab_part[NCH * BN * KK * HW];   // 13.2 MB partial ab
__device__ float g_asq[KK];
__device__ float g_g[BN * CC];                    // sum_k feat_mod

// ---------------------------------------------------------------------------
// f32x2 + cp.async helpers
// ---------------------------------------------------------------------------
__device__ __forceinline__ void ffma2(ull& d, ull a, ull b) {
    asm("fma.rn.f32x2 %0, %1, %2, %0;" : "+l"(d) : "l"(a), "l"(b));
}
__device__ __forceinline__ ull pack2(float lo, float hi) {
    ull r; asm("mov.b64 %0, {%1, %2};" : "=l"(r) : "f"(lo), "f"(hi)); return r;
}
__device__ __forceinline__ float2 unpack2(ull v) {
    float2 r; asm("mov.b64 {%0, %1}, %2;" : "=f"(r.x), "=f"(r.y) : "l"(v)); return r;
}
__device__ __forceinline__ void cp16(uint32_t smem_dst, const void* gsrc) {
    asm volatile("cp.async.cg.shared.global [%0], [%1], 16;"
                 :: "r"(smem_dst), "l"(gsrc));
}
__device__ __forceinline__ void cp_commit() {
    asm volatile("cp.async.commit_group;");
}
template <int N>
__device__ __forceinline__ void cp_wait() {
    asm volatile("cp.async.wait_group %0;" :: "n"(N));
}
__device__ __forceinline__ uint32_t sptr(const void* p) {
    return (uint32_t)__cvta_generic_to_shared(p);
}

// ---------------------------------------------------------------------------
// Kernel 0: a_sq[k] = sum_c w_land[k,c]^2
// ---------------------------------------------------------------------------
__global__ void k_asq(const float* __restrict__ wl) {
    int k = blockIdx.x;
    int tid = threadIdx.x;
    float s = 0.f;
    for (int c = tid; c < CC; c += 128) {
        float w = wl[k * CC + c];
        s += w * w;
    }
    __shared__ float red[128];
    red[tid] = s;
    __syncthreads();
    for (int o = 64; o; o >>= 1) {
        if (tid < o) red[tid] += red[tid + o];
        __syncthreads();
    }
    if (tid == 0) g_asq[k] = red[0];
}

// ---------------------------------------------------------------------------
// Kernel 1: SELF-SERVICE partial ab. grid (NCH=12, BN), block 196.
// Thread owns pixel-quad tid (float4). Per stage (4 channels) the thread
// cp.asyncs its OWN quad for each channel into its private smem slot, then
// reads it back itself -> NO per-stage __syncthreads. Ring of 4 stages,
// wait_group<2> => 3 stages (192 B/thread) in flight, always.
// Smem: ws2 22528 + 4 x 12544 = 72704 B -> 3 blocks/SM, grid fits 1 wave.
// ---------------------------------------------------------------------------
#define AB_SCH    4
#define AB_STAGES (CCH / AB_SCH)   // 64
__global__ void __launch_bounds__(196, 3) k_ab(const float* __restrict__ x,
                                               const float* __restrict__ wl) {
    extern __shared__ char smem_ab[];
    ull* ws2 = (ull*)smem_ab;                       // [KK*CCH] {w,w} 22528 B
    char* xr = smem_ab + 22528;                     // ring: 4 x 12544 B

    const int ch = blockIdx.x;
    const int b  = blockIdx.y;
    const int c0 = ch * CCH;
    const int tid = threadIdx.x;

    const float4* x4 = (const float4*)x;
    const float4* xbase = x4 + ((size_t)b * CC + c0) * 196 + tid;

#define AB_KICK(s) {                                                          \
        uint32_t d_ = sptr(xr + ((s) & 3) * 12544) + tid * 16;                \
        const float4* src_ = xbase + (size_t)((s) * AB_SCH) * 196;            \
        cp16(d_ + 0 * 3136, src_ + 0 * 196);                                  \
        cp16(d_ + 1 * 3136, src_ + 1 * 196);                                  \
        cp16(d_ + 2 * 3136, src_ + 2 * 196);                                  \
        cp16(d_ + 3 * 3136, src_ + 3 * 196);                                  \
        cp_commit();                                                          \
    }

    AB_KICK(0); AB_KICK(1); AB_KICK(2);

    // weights as duplicated pairs {w,w}
    for (int i = tid; i < KK * CCH; i += 196) {
        int k = i >> 8, c = i & (CCH - 1);
        float w = wl[k * CC + c0 + c];
        ws2[i] = pack2(w, w);
    }
    __syncthreads();    // only for ws2 visibility (once)

    ull acc[KK][2];
#pragma unroll
    for (int k = 0; k < KK; ++k) { acc[k][0] = 0ull; acc[k][1] = 0ull; }

    const ulonglong2* ws22 = (const ulonglong2*)ws2;   // [KK][CCH/2]

#pragma unroll 1
    for (int s = 0; s < AB_STAGES; ++s) {
        if (s <= AB_STAGES - 3)      cp_wait<2>();
        else if (s == AB_STAGES - 2) cp_wait<1>();
        else                         cp_wait<0>();

        const ulonglong2* xq = (const ulonglong2*)(xr + (s & 3) * 12544);
        ulonglong2 x0 = xq[0 * 196 + tid];     // own quad, 4 channels
        ulonglong2 x1 = xq[1 * 196 + tid];
        ulonglong2 x2 = xq[2 * 196 + tid];
        ulonglong2 x3 = xq[3 * 196 + tid];
#pragma unroll
        for (int k = 0; k < KK; ++k) {
            ulonglong2 w01 = ws22[k * (CCH / 2) + 2 * s];       // ch 0,1
            ulonglong2 w23 = ws22[k * (CCH / 2) + 2 * s + 1];   // ch 2,3
            ffma2(acc[k][0], x0.x, w01.x); ffma2(acc[k][1], x0.y, w01.x);
            ffma2(acc[k][0], x1.x, w01.y); ffma2(acc[k][1], x1.y, w01.y);
            ffma2(acc[k][0], x2.x, w23.x); ffma2(acc[k][1], x2.y, w23.x);
            ffma2(acc[k][0], x3.x, w23.y); ffma2(acc[k][1], x3.y, w23.y);
        }

        if (s + 3 < AB_STAGES) AB_KICK(s + 3);
    }

    ulonglong2* gp2 = reinterpret_cast<ulonglong2*>(g_ab_part);
    size_t base2 = (size_t)(ch * BN + b) * KK * 196;
#pragma unroll
    for (int k = 0; k < KK; ++k) {
        ulonglong2 v; v.x = acc[k][0]; v.y = acc[k][1];
        gp2[base2 + (size_t)k * 196 + tid] = v;
    }
#undef AB_KICK
}

// ---------------------------------------------------------------------------
// Kernel 2: combine chunks, softmax over K (b_sq cancels), write maps.
// grid (BN, 4 pixel slices), block 196 (1 pixel per thread)
// ---------------------------------------------------------------------------
__global__ void k_softmax(float* __restrict__ maps) {
    const int b = blockIdx.x;
    const int p = blockIdx.y * 196 + threadIdx.x;

    __shared__ float asq[KK];
    if (threadIdx.x < KK) asq[threadIdx.x] = g_asq[threadIdx.x];
    __syncthreads();

    float s[KK];
#pragma unroll
    for (int k = 0; k < KK; ++k) s[k] = 0.f;

#pragma unroll
    for (int ch = 0; ch < NCH; ++ch) {
        size_t base = ((size_t)(ch * BN + b) * KK) * HW + p;
#pragma unroll
        for (int k = 0; k < KK; ++k)
            s[k] += g_ab_part[base + (size_t)k * HW];
    }
    float mx = -1e30f;
#pragma unroll
    for (int k = 0; k < KK; ++k) {
        s[k] = 2.f * s[k] - asq[k];
        mx = fmaxf(mx, s[k]);
    }
    float sum = 0.f;
#pragma unroll
    for (int k = 0; k < KK; ++k) {
        s[k] = __expf(s[k] - mx);
        sum += s[k];
    }
    float inv = 1.f / sum;
#pragma unroll
    for (int k = 0; k < KK; ++k)
        maps[((size_t)(b * KK + k)) * HW + p] = s[k] * inv;
}

// ---------------------------------------------------------------------------
// Kernel 3: SELF-SERVICE feat. grid (12, BN), block 256. Thread owns ONE
// channel c = bx*256 + tid: it cp.asyncs its own channel's pixels (8 px =
// 2 float4 per stage) into its private smem slot and consumes them itself.
// maps stay in smem (loaded once) and are pure broadcast LDS.128. No
// per-stage barriers, no cross-thread reduction (thread owns full feat row).
// Smem: maps 34496 + 4 x 8192 = 67264 B -> 3 blocks/SM, single wave.
// ---------------------------------------------------------------------------
#define FT_STAGES 98     // 784 px / 8
__global__ void __launch_bounds__(256, 3) k_feat(const float* __restrict__ x,
                                                 const float* __restrict__ maps,
                                                 const float* __restrict__ mod,
                                                 float* __restrict__ feat) {
    extern __shared__ char smem_ft[];
    ull* maps_s = (ull*)smem_ft;                    // [KK*392] 34496 B
    char* xr = smem_ft + 34496;                     // ring: 4 x 8192 B

    const int b   = (BN - 1) - blockIdx.y;          // reversed for L2 overlap
    const int tid = threadIdx.x;
    const int c   = blockIdx.x * 256 + tid;

    const float4* xrow = (const float4*)x + ((size_t)b * CC + c) * 196;

#define FT_KICK(s) {                                                          \
        uint32_t d_ = sptr(xr + ((s) & 3) * 8192) + tid * 16;                 \
        cp16(d_,        xrow + (s) * 2);                                      \
        cp16(d_ + 4096, xrow + (s) * 2 + 1);                                  \
        cp_commit();                                                          \
    }

    FT_KICK(0); FT_KICK(1); FT_KICK(2);

    // maps into smem while first stages fly (one-time sync)
    const ull* mg = reinterpret_cast<const ull*>(maps + (size_t)b * KK * HW);
    for (int i = tid; i < KK * 392; i += 256) maps_s[i] = mg[i];
    __syncthreads();

    ull acc[KK];
#pragma unroll
    for (int k = 0; k < KK; ++k) acc[k] = 0ull;

    const ulonglong2* m2 = (const ulonglong2*)maps_s;   // [KK][196]

#pragma unroll 1
    for (int s = 0; s < FT_STAGES; ++s) {
        if (s <= FT_STAGES - 3)      cp_wait<2>();
        else if (s == FT_STAGES - 2) cp_wait<1>();
        else                         cp_wait<0>();

        const char* xb_ = xr + (s & 3) * 8192;
        ulonglong2 xq0 = *(const ulonglong2*)(xb_ + tid * 16);          // px 8s..8s+3
        ulonglong2 xq1 = *(const ulonglong2*)(xb_ + 4096 + tid * 16);   // px 8s+4..8s+7
#pragma unroll
        for (int k = 0; k < KK; ++k) {
            ulonglong2 m0 = m2[k * 196 + 2 * s];       // broadcast
            ulonglong2 m1 = m2[k * 196 + 2 * s + 1];
            ffma2(acc[k], xq0.x, m0.x); ffma2(acc[k], xq0.y, m0.y);
            ffma2(acc[k], xq1.x, m1.x); ffma2(acc[k], xq1.y, m1.y);
        }

        if (s + 3 < FT_STAGES) FT_KICK(s + 3);
    }

    const float inv_hw = 1.f / (float)HW;
    float gs = 0.f;
    float* frow = feat + ((size_t)b * CC + c) * KK;
    const float* mrow = mod + (size_t)c * KK;
#pragma unroll
    for (int k = 0; k < KK; ++k) {
        float2 v = unpack2(acc[k]);
        float r = (v.x + v.y) * inv_hw * mrow[k];
        frow[k] = r;
        gs += r;
    }
    g_g[b * CC + c] = gs;
#undef FT_KICK
}

// ---------------------------------------------------------------------------
// Kernel 4: attn[b,k] = sum_p maps[b,k,p].  grid (BN, KK), block 256
// ---------------------------------------------------------------------------
__global__ void k_attn(const float* __restrict__ maps, float* __restrict__ attn) {
    const int b = blockIdx.x, k = blockIdx.y, tid = threadIdx.x;
    float s = 0.f;
    const float* mp = maps + ((size_t)b * KK + k) * HW;
    for (int i = tid; i < HW; i += 256) s += mp[i];
    __shared__ float red[256];
    red[tid] = s;
    __syncthreads();
    for (int o = 128; o; o >>= 1) {
        if (tid < o) red[tid] += red[tid + o];
        __syncthreads();
    }
    if (tid == 0) attn[b * KK + k] = red[0];
}

// ---------------------------------------------------------------------------
// Kernel 5: scores[b,n] = sum_c g[b,c] * w_cls[n,c]; 4 batches per block.
// grid (NCLS, BN/4), block 128
// ---------------------------------------------------------------------------
__global__ void k_scores(const float* __restrict__ wcls,
                         float* __restrict__ scores) {
    const int n = blockIdx.x;
    const int b0 = blockIdx.y * 4;
    const int tid = threadIdx.x;
    float s0 = 0.f, s1 = 0.f, s2 = 0.f, s3 = 0.f;
    const float* wn = wcls + (size_t)n * CC;
    for (int c = tid; c < CC; c += 128) {
        float w = wn[c];
        s0 = fmaf(w, g_g[(b0 + 0) * CC + c], s0);
        s1 = fmaf(w, g_g[(b0 + 1) * CC + c], s1);
        s2 = fmaf(w, g_g[(b0 + 2) * CC + c], s2);
        s3 = fmaf(w, g_g[(b0 + 3) * CC + c], s3);
    }
    __shared__ float red[4][128];
    red[0][tid] = s0; red[1][tid] = s1; red[2][tid] = s2; red[3][tid] = s3;
    __syncthreads();
    for (int o = 64; o; o >>= 1) {
        if (tid < o) {
            red[0][tid] += red[0][tid + o];
            red[1][tid] += red[1][tid + o];
            red[2][tid] += red[2][tid + o];
            red[3][tid] += red[3][tid + o];
        }
        __syncthreads();
    }
    if (tid == 0) {
#pragma unroll
        for (int j = 0; j < 4; ++j)
            scores[(b0 + j) * NCLS + n] = red[j][0];
    }
}

// ---------------------------------------------------------------------------
extern "C" void kernel_launch(void* const* d_in, const int* in_sizes, int n_in,
                              void* d_out, int out_size) {
    const float* x    = (const float*)d_in[0];
    const float* wl   = (const float*)d_in[1];
    const float* mod  = (const float*)d_in[2];
    const float* wcls = (const float*)d_in[3];

    float* out    = (float*)d_out;
    float* feat   = out;                                   // (B,C,K)
    float* scores = out + (size_t)BN * CC * KK;            // (B,NC)
    float* maps   = scores + (size_t)BN * NCLS;            // (B,K,HW)
    float* attn   = maps + (size_t)BN * KK * HW;           // (B,K)

    cudaFuncSetAttribute(k_ab,   cudaFuncAttributeMaxDynamicSharedMemorySize, 72704);
    cudaFuncSetAttribute(k_feat, cudaFuncAttributeMaxDynamicSharedMemorySize, 67264);

    k_asq<<<KK, 128>>>(wl);
    k_ab<<<dim3(NCH, BN), 196, 72704>>>(x, wl);
    k_softmax<<<dim3(BN, 4), 196>>>(maps);
    k_feat<<<dim3(CC / 256, BN), 256, 67264>>>(x, maps, mod, feat);
    k_attn<<<dim3(BN, KK), 256>>>(maps, attn);
    k_scores<<<dim3(NCLS, BN / 4), 128>>>(wcls, scores);
}